// round 1
// baseline (speedup 1.0000x reference)
#include <cuda_runtime.h>
#include <math.h>

#define BD  2
#define CD  96
#define HD  64
#define WD  64
#define LD  4096
#define DI  192
#define DTR 6
#define DS  16
#define HIDN 192
#define NC  64
#define CT  64

// ---------------- scratch (device globals; no allocation in kernel_launch) ----------------
__device__ float g_x1  [BD*CD*LD];
__device__ float g_xn  [BD*LD*CD];
__device__ float g_xz  [2][(long)BD*LD*384];
__device__ float g_xs  [2][(long)BD*LD*DI];
__device__ float g_xdbl[2][(long)BD*LD*38];
__device__ float g_delta[2][(long)BD*LD*DI];
__device__ float g_chH [2][(long)BD*NC*DI*DS];
__device__ float g_chD [2][(long)BD*NC*DI];
__device__ float g_comb[(long)BD*LD*DI];
__device__ float g_yo  [(long)BD*LD*CD];
__device__ float g_xmid[(long)BD*CD*LD];
__device__ float g_xm  [(long)BD*LD*CD];
__device__ float g_hbuf[(long)BD*3*HIDN*LD];
__device__ float g_gg  [(long)BD*HIDN*LD];

// ---------------- helpers ----------------
__device__ __forceinline__ float wsum(float v) {
#pragma unroll
    for (int o = 16; o > 0; o >>= 1) v += __shfl_xor_sync(0xffffffffu, v, o);
    return v;
}

// ---------------- fused double LayerNorm: x -> x1 (B,C,L), xn (B,L,C) ----------------
__global__ void __launch_bounds__(256) ln_double_k(
    const float* __restrict__ x,
    const float* __restrict__ w1, const float* __restrict__ b1,
    const float* __restrict__ w2, const float* __restrict__ b2)
{
    int gw = (blockIdx.x * 256 + threadIdx.x) >> 5;   // warp = one (b,l)
    int lane = threadIdx.x & 31;
    int b = gw >> 12;
    int l = gw & 4095;
    const float* xp = x + (long)b * CD * LD + l;
    float v[3];
#pragma unroll
    for (int i = 0; i < 3; i++) v[i] = xp[(long)(lane + 32 * i) * LD];
    float u = wsum(v[0] + v[1] + v[2]) * (1.f / 96.f);
    float q = 0.f;
#pragma unroll
    for (int i = 0; i < 3; i++) { float t = v[i] - u; q += t * t; }
    q = wsum(q);
    float rs = rsqrtf(q * (1.f / 96.f) + 1e-6f);
    float x1v[3];
    float* x1p = g_x1 + (long)b * CD * LD + l;
#pragma unroll
    for (int i = 0; i < 3; i++) {
        int cc = lane + 32 * i;
        x1v[i] = w1[cc] * (v[i] - u) * rs + b1[cc];
        x1p[(long)cc * LD] = x1v[i];
    }
    float u2 = wsum(x1v[0] + x1v[1] + x1v[2]) * (1.f / 96.f);
    float q2 = 0.f;
#pragma unroll
    for (int i = 0; i < 3; i++) { float t = x1v[i] - u2; q2 += t * t; }
    q2 = wsum(q2);
    float rs2 = rsqrtf(q2 * (1.f / 96.f) + 1e-5f);
    float* xnp = g_xn + ((long)b * LD + l) * CD;
#pragma unroll
    for (int i = 0; i < 3; i++) {
        int cc = lane + 32 * i;
        xnp[cc] = (x1v[i] - u2) * rs2 * w2[cc] + b2[cc];
    }
}

// ---------------- single channel-LN: g_xmid -> g_xm (B,L,C) ----------------
__global__ void __launch_bounds__(256) ln_single_k(
    const float* __restrict__ w1, const float* __restrict__ b1)
{
    int gw = (blockIdx.x * 256 + threadIdx.x) >> 5;
    int lane = threadIdx.x & 31;
    int b = gw >> 12;
    int l = gw & 4095;
    const float* xp = g_xmid + (long)b * CD * LD + l;
    float v[3];
#pragma unroll
    for (int i = 0; i < 3; i++) v[i] = xp[(long)(lane + 32 * i) * LD];
    float u = wsum(v[0] + v[1] + v[2]) * (1.f / 96.f);
    float q = 0.f;
#pragma unroll
    for (int i = 0; i < 3; i++) { float t = v[i] - u; q += t * t; }
    q = wsum(q);
    float rs = rsqrtf(q * (1.f / 96.f) + 1e-6f);
    float* xmp = g_xm + ((long)b * LD + l) * CD;
#pragma unroll
    for (int i = 0; i < 3; i++) {
        int cc = lane + 32 * i;
        xmp[cc] = w1[cc] * (v[i] - u) * rs + b1[cc];
    }
}

// ---------------- generic SGEMM: C[M,N] = A[M,K] * (BT ? B[N,K]^T : B[K,N]) ----------------
// 64x64 tile, BK=16, 256 threads, 4x4 microtile. Requires K%16==0, K%4==0.
// EPI==1: C[m,n] = resid[m,n] + gmul[m]*acc (final fused residual).
template<bool BT, int EPI>
__global__ void __launch_bounds__(256) gemm_k(
    const float* __restrict__ A, const float* __restrict__ B, float* __restrict__ C,
    int M, int N, int K, long sA, long sB, long sC,
    const float* __restrict__ gmul, const float* __restrict__ resid, long sR)
{
    __shared__ __align__(16) float As[16][64];
    __shared__ __align__(16) float Bs[16][64];
    A += (long)blockIdx.z * sA;
    B += (long)blockIdx.z * sB;
    C += (long)blockIdx.z * sC;
    if (EPI) resid += (long)blockIdx.z * sR;
    const int tid = threadIdx.x;
    const int m0 = blockIdx.y << 6, n0 = blockIdx.x << 6;
    const int ty = tid >> 4, tx = tid & 15;
    const int ar = tid >> 2, ac = (tid & 3) << 2;
    const int br = tid >> 4, bc = (tid & 15) << 2;
    float acc[4][4];
#pragma unroll
    for (int i = 0; i < 4; i++)
#pragma unroll
        for (int j = 0; j < 4; j++) acc[i][j] = 0.f;

    for (int k0 = 0; k0 < K; k0 += 16) {
        float4 av = make_float4(0.f, 0.f, 0.f, 0.f);
        if (m0 + ar < M) av = *(const float4*)(A + (long)(m0 + ar) * K + k0 + ac);
        As[ac + 0][ar] = av.x; As[ac + 1][ar] = av.y;
        As[ac + 2][ar] = av.z; As[ac + 3][ar] = av.w;
        if (BT) {
            float4 bv = make_float4(0.f, 0.f, 0.f, 0.f);
            if (n0 + ar < N) bv = *(const float4*)(B + (long)(n0 + ar) * K + k0 + ac);
            Bs[ac + 0][ar] = bv.x; Bs[ac + 1][ar] = bv.y;
            Bs[ac + 2][ar] = bv.z; Bs[ac + 3][ar] = bv.w;
        } else {
            float4 bv = make_float4(0.f, 0.f, 0.f, 0.f);
            if (n0 + bc < N) bv = *(const float4*)(B + (long)(k0 + br) * N + n0 + bc);
            *(float4*)&Bs[br][bc] = bv;
        }
        __syncthreads();
#pragma unroll
        for (int kk = 0; kk < 16; kk++) {
            float4 a  = *(const float4*)&As[kk][ty << 2];
            float4 b4 = *(const float4*)&Bs[kk][tx << 2];
            acc[0][0] += a.x * b4.x; acc[0][1] += a.x * b4.y; acc[0][2] += a.x * b4.z; acc[0][3] += a.x * b4.w;
            acc[1][0] += a.y * b4.x; acc[1][1] += a.y * b4.y; acc[1][2] += a.y * b4.z; acc[1][3] += a.y * b4.w;
            acc[2][0] += a.z * b4.x; acc[2][1] += a.z * b4.y; acc[2][2] += a.z * b4.z; acc[2][3] += a.z * b4.w;
            acc[3][0] += a.w * b4.x; acc[3][1] += a.w * b4.y; acc[3][2] += a.w * b4.z; acc[3][3] += a.w * b4.w;
        }
        __syncthreads();
    }
#pragma unroll
    for (int i = 0; i < 4; i++) {
        int m = m0 + (ty << 2) + i;
        if (m >= M) continue;
#pragma unroll
        for (int j = 0; j < 4; j++) {
            int n = n0 + (tx << 2) + j;
            if (n >= N) continue;
            float v = acc[i][j];
            if (EPI) v = resid[(long)m * N + n] + gmul[m] * v;
            C[(long)m * N + n] = v;
        }
    }
}

// ---------------- causal depthwise conv(k=4) + SiLU; dir=1 reads reversed sequence ----------------
__global__ void __launch_bounds__(256) conv_silu_k(
    int dir, const float* __restrict__ cw, const float* __restrict__ cb)
{
    long idx = (long)blockIdx.x * 256 + threadIdx.x;   // B*L*DI
    int d = (int)(idx % DI);
    int t = (int)((idx / DI) % LD);
    int b = (int)(idx / ((long)DI * LD));
    float acc = cb[d];
#pragma unroll
    for (int k = 0; k < 4; k++) {
        int tt = t - 3 + k;
        if (tt >= 0) {
            int l = dir ? (LD - 1 - tt) : tt;
            acc += cw[d * 4 + k] * g_xz[dir][((long)b * LD + l) * 384 + d];
        }
    }
    g_xs[dir][idx] = acc / (1.f + __expf(-acc));
}

// ---------------- delta = softplus(dt @ Wdt^T + bdt) ----------------
__global__ void __launch_bounds__(256) delta_k(
    int dir, const float* __restrict__ Wdt, const float* __restrict__ bdt)
{
    long idx = (long)blockIdx.x * 256 + threadIdx.x;   // B*L*DI
    int d = (int)(idx % DI);
    long bt = idx / DI;
    const float* row = g_xdbl[dir] + bt * 38;
    float acc = bdt[d];
#pragma unroll
    for (int r = 0; r < 6; r++) acc += row[r] * Wdt[d * 6 + r];
    g_delta[dir][idx] = (acc > 20.f) ? acc : log1pf(__expf(acc));
}

// ---------------- chunked selective scan, phase 1: per-chunk local state + sum(delta) ----------------
__global__ void __launch_bounds__(192) scan_p1(int dir, const float* __restrict__ Alog)
{
    int c = blockIdx.x, b = blockIdx.y, d = threadIdx.x;
    __shared__ __align__(16) float sB[CT * 16];
    const float* xd = g_xdbl[dir] + ((long)b * LD + (long)c * CT) * 38;
    for (int i = d; i < CT * 16; i += 192) {
        int t = i >> 4, s = i & 15;
        sB[i] = xd[t * 38 + 6 + s];
    }
    float Ad[16];
#pragma unroll
    for (int s = 0; s < 16; s++) Ad[s] = -__expf(Alog[d * 16 + s]);
    __syncthreads();
    float h[16];
#pragma unroll
    for (int s = 0; s < 16; s++) h[s] = 0.f;
    float sd = 0.f;
    const float* dp = g_delta[dir] + ((long)b * LD + (long)c * CT) * DI + d;
    const float* xp = g_xs[dir]    + ((long)b * LD + (long)c * CT) * DI + d;
    for (int t = 0; t < CT; t++) {
        float dl = dp[(long)t * DI];
        float xv = xp[(long)t * DI];
        float u = dl * xv;
        sd += dl;
        const float* bt = &sB[t * 16];
#pragma unroll
        for (int s = 0; s < 16; s++)
            h[s] = __expf(Ad[s] * dl) * h[s] + u * bt[s];
    }
    float* hp = g_chH[dir] + (((long)b * NC + c) * DI + d) * 16;
#pragma unroll
    for (int s = 0; s < 16; s++) hp[s] = h[s];
    g_chD[dir][((long)b * NC + c) * DI + d] = sd;
}

// ---------------- phase 2: sequential inter-chunk combine (in-place: chH becomes h_start) ----------------
__global__ void __launch_bounds__(192) scan_p2(
    const float* __restrict__ AlogF, const float* __restrict__ AlogB)
{
    int b = blockIdx.x, dir = blockIdx.y, d = threadIdx.x;
    const float* Alog = dir ? AlogB : AlogF;
    float Ad[16];
#pragma unroll
    for (int s = 0; s < 16; s++) Ad[s] = -__expf(Alog[d * 16 + s]);
    float h[16];
#pragma unroll
    for (int s = 0; s < 16; s++) h[s] = 0.f;
    for (int c = 0; c < NC; c++) {
        float sd = g_chD[dir][((long)b * NC + c) * DI + d];
        float* hp = g_chH[dir] + (((long)b * NC + c) * DI + d) * 16;
#pragma unroll
        for (int s = 0; s < 16; s++) {
            float a = __expf(Ad[s] * sd);
            float loc = hp[s];
            hp[s] = h[s];                // store h_start for this chunk
            h[s] = a * h[s] + loc;
        }
    }
}

// ---------------- phase 3: recompute with correct h_start, emit y*silu(z) into comb ----------------
__global__ void __launch_bounds__(192) scan_p3(
    int dir, const float* __restrict__ Alog, const float* __restrict__ Dp)
{
    int c = blockIdx.x, b = blockIdx.y, d = threadIdx.x;
    __shared__ __align__(16) float sB[CT * 16];
    __shared__ __align__(16) float sC[CT * 16];
    const float* xd = g_xdbl[dir] + ((long)b * LD + (long)c * CT) * 38;
    for (int i = d; i < CT * 16; i += 192) {
        int t = i >> 4, s = i & 15;
        sB[i] = xd[t * 38 + 6 + s];
        sC[i] = xd[t * 38 + 22 + s];
    }
    float Ad[16];
#pragma unroll
    for (int s = 0; s < 16; s++) Ad[s] = -__expf(Alog[d * 16 + s]);
    float Dd = Dp[d];
    __syncthreads();
    const float* hp = g_chH[dir] + (((long)b * NC + c) * DI + d) * 16;
    float h[16];
#pragma unroll
    for (int s = 0; s < 16; s++) h[s] = hp[s];
    const float* dp = g_delta[dir] + ((long)b * LD + (long)c * CT) * DI + d;
    const float* xp = g_xs[dir]    + ((long)b * LD + (long)c * CT) * DI + d;
    for (int t = 0; t < CT; t++) {
        float dl = dp[(long)t * DI];
        float xv = xp[(long)t * DI];
        float u = dl * xv;
        const float* bt = &sB[t * 16];
        const float* ct = &sC[t * 16];
        float y = 0.f;
#pragma unroll
        for (int s = 0; s < 16; s++) {
            h[s] = __expf(Ad[s] * dl) * h[s] + u * bt[s];
            y += h[s] * ct[s];
        }
        int tg = c * CT + t;
        int lo = dir ? (LD - 1 - tg) : tg;
        float zv = g_xz[dir][((long)b * LD + lo) * 384 + 192 + d];
        float val = (y + xv * Dd) * (zv / (1.f + __expf(-zv)));
        long oi = ((long)b * LD + lo) * DI + d;
        if (dir) g_comb[oi] += val;
        else     g_comb[oi] = val;
    }
}

// ---------------- residual 1: xmid = x + gamma1*(yo + x1) ----------------
__global__ void __launch_bounds__(256) resid1_k(
    const float* __restrict__ x, const float* __restrict__ gamma1)
{
    long idx = (long)blockIdx.x * 256 + threadIdx.x;   // B*C*L
    int l = (int)(idx % LD);
    int c = (int)((idx / LD) % CD);
    int b = (int)(idx / ((long)CD * LD));
    float yov = g_yo[((long)b * LD + l) * CD + c];
    g_xmid[idx] = x[idx] + gamma1[c] * (yov + g_x1[idx]);
}

// ---------------- MSFF gate: g = gelu(dw1(h1)) * dw2(h2) * dw3(h3) ----------------
__device__ __forceinline__ float dwc9(const float* __restrict__ p,
                                      const float* __restrict__ w,
                                      int y, int x, int dil)
{
    float acc = 0.f;
#pragma unroll
    for (int ky = 0; ky < 3; ky++) {
        int yy = y + (ky - 1) * dil;
        if (yy < 0 || yy >= HD) continue;
#pragma unroll
        for (int kx = 0; kx < 3; kx++) {
            int xx = x + (kx - 1) * dil;
            if (xx < 0 || xx >= WD) continue;
            acc += w[ky * 3 + kx] * p[yy * WD + xx];
        }
    }
    return acc;
}

__global__ void __launch_bounds__(256) gate_k(
    const float* __restrict__ dw1, const float* __restrict__ dw2, const float* __restrict__ dw3)
{
    long idx = (long)blockIdx.x * 256 + threadIdx.x;   // B*HIDN*L
    int l = (int)(idx % LD);
    int j = (int)((idx / LD) % HIDN);
    int b = (int)(idx / ((long)HIDN * LD));
    int y = l >> 6, x = l & 63;
    const float* hb = g_hbuf + (long)b * 3 * HIDN * LD;
    float a1 = dwc9(hb + (long)j * LD,              dw1 + j * 9, y, x, 1);
    float a2 = dwc9(hb + (long)(HIDN + j) * LD,     dw2 + j * 9, y, x, 2);
    float a3 = dwc9(hb + (long)(2 * HIDN + j) * LD, dw3 + j * 9, y, x, 3);
    float ge = 0.5f * a1 * (1.f + erff(a1 * 0.70710678118654752f));
    g_gg[idx] = ge * a2 * a3;
}

// ---------------- host ----------------
extern "C" void kernel_launch(void* const* d_in, const int* in_sizes, int n_in,
                              void* d_out, int out_size)
{
    const float* x      = (const float*)d_in[0];
    const float* gamma1 = (const float*)d_in[1];
    const float* gamma2 = (const float*)d_in[2];
    const float* ln1w   = (const float*)d_in[3];
    const float* ln1b   = (const float*)d_in[4];
    const float* mnw    = (const float*)d_in[5];
    const float* mnb    = (const float*)d_in[6];
    const float* Win[2]   = {(const float*)d_in[7],  (const float*)d_in[15]};
    const float* convw[2] = {(const float*)d_in[8],  (const float*)d_in[16]};
    const float* convb[2] = {(const float*)d_in[9],  (const float*)d_in[17]};
    const float* Wx[2]    = {(const float*)d_in[10], (const float*)d_in[18]};
    const float* Wdt[2]   = {(const float*)d_in[11], (const float*)d_in[19]};
    const float* bdt[2]   = {(const float*)d_in[12], (const float*)d_in[20]};
    const float* Alog[2]  = {(const float*)d_in[13], (const float*)d_in[21]};
    const float* Dp[2]    = {(const float*)d_in[14], (const float*)d_in[22]};
    const float* Wout   = (const float*)d_in[23];
    const float* mwin   = (const float*)d_in[24];
    const float* dw1    = (const float*)d_in[25];
    const float* dw2    = (const float*)d_in[26];
    const float* dw3    = (const float*)d_in[27];
    const float* mwout  = (const float*)d_in[28];
    float* out = (float*)d_out;

    float *p_xn, *p_xz, *p_xs, *p_xdbl, *p_comb, *p_yo, *p_xm, *p_hbuf, *p_gg, *p_xmid;
    cudaGetSymbolAddress((void**)&p_xn,   g_xn);
    cudaGetSymbolAddress((void**)&p_xz,   g_xz);
    cudaGetSymbolAddress((void**)&p_xs,   g_xs);
    cudaGetSymbolAddress((void**)&p_xdbl, g_xdbl);
    cudaGetSymbolAddress((void**)&p_comb, g_comb);
    cudaGetSymbolAddress((void**)&p_yo,   g_yo);
    cudaGetSymbolAddress((void**)&p_xm,   g_xm);
    cudaGetSymbolAddress((void**)&p_hbuf, g_hbuf);
    cudaGetSymbolAddress((void**)&p_gg,   g_gg);
    cudaGetSymbolAddress((void**)&p_xmid, g_xmid);

    const long XZS = (long)BD * LD * 384;
    const long XSS = (long)BD * LD * DI;
    const long XDS = (long)BD * LD * 38;

    // 1. LN pair
    ln_double_k<<<1024, 256>>>(x, ln1w, ln1b, mnw, mnb);

    // 2. xz = xn @ Win^T (per direction)
    for (int dir = 0; dir < 2; dir++)
        gemm_k<true, 0><<<dim3(6, 128, 1), 256>>>(
            p_xn, Win[dir], p_xz + dir * XZS, BD * LD, 384, CD, 0, 0, 0, nullptr, nullptr, 0);

    // 3. causal conv + silu
    for (int dir = 0; dir < 2; dir++)
        conv_silu_k<<<(int)(((long)BD * LD * DI) / 256), 256>>>(dir, convw[dir], convb[dir]);

    // 4. x_dbl = xs @ Wx^T
    for (int dir = 0; dir < 2; dir++)
        gemm_k<true, 0><<<dim3(1, 128, 1), 256>>>(
            p_xs + dir * XSS, Wx[dir], p_xdbl + dir * XDS, BD * LD, 38, DI, 0, 0, 0, nullptr, nullptr, 0);

    // 5. delta
    for (int dir = 0; dir < 2; dir++)
        delta_k<<<(int)(((long)BD * LD * DI) / 256), 256>>>(dir, Wdt[dir], bdt[dir]);

    // 6. chunked scan
    for (int dir = 0; dir < 2; dir++)
        scan_p1<<<dim3(NC, BD), 192>>>(dir, Alog[dir]);
    scan_p2<<<dim3(BD, 2), 192>>>(Alog[0], Alog[1]);
    scan_p3<<<dim3(NC, BD), 192>>>(0, Alog[0], Dp[0]);
    scan_p3<<<dim3(NC, BD), 192>>>(1, Alog[1], Dp[1]);

    // 7. yo = comb @ Wout^T
    gemm_k<true, 0><<<dim3(2, 128, 1), 256>>>(
        p_comb, Wout, p_yo, BD * LD, CD, DI, 0, 0, 0, nullptr, nullptr, 0);

    // 8. first residual
    resid1_k<<<(int)(((long)BD * CD * LD) / 256), 256>>>(x, gamma1);

    // 9. xm = ln_cf(xmid)
    ln_single_k<<<1024, 256>>>(ln1w, ln1b);

    // 10. h = msff_win @ xm^T  (batched, output (B, 576, L))
    gemm_k<true, 0><<<dim3(64, 9, BD), 256>>>(
        mwin, p_xm, p_hbuf, 3 * HIDN, LD, CD,
        0, (long)LD * CD, (long)3 * HIDN * LD, nullptr, nullptr, 0);

    // 11. gated multiscale dwconv
    gate_k<<<(int)(((long)BD * HIDN * LD) / 256), 256>>>(dw1, dw2, dw3);

    // 12. out = xmid + gamma2 * (msff_wout @ g)   (batched, fused residual)
    gemm_k<false, 1><<<dim3(64, 2, BD), 256>>>(
        mwout, p_gg, out, CD, LD, HIDN,
        0, (long)HIDN * LD, (long)CD * LD, gamma2, p_xmid, (long)CD * LD);
}

// round 2
// speedup vs baseline: 1.0134x; 1.0134x over previous
#include <cuda_runtime.h>
#include <math.h>

#define BD  2
#define CD  96
#define HD  64
#define WD  64
#define LD  4096
#define DI  192
#define DTR 6
#define DS  16
#define HIDN 192
#define NC  64
#define CT  64

// ---------------- scratch (device globals; no allocation in kernel_launch) ----------------
__device__ float g_x1  [BD*CD*LD];
__device__ float g_xn  [BD*LD*CD];
__device__ float g_xz  [2][(long)BD*LD*384];
__device__ float g_xs  [2][(long)BD*LD*DI];
__device__ float g_xdbl[2][(long)BD*LD*38];
__device__ float g_delta[2][(long)BD*LD*DI];
__device__ float g_chH [2][(long)BD*NC*DI*DS];
__device__ float g_chD [2][(long)BD*NC*DI];
__device__ float g_comb[(long)BD*LD*DI];
__device__ float g_yo  [(long)BD*LD*CD];
__device__ float g_xmid[(long)BD*CD*LD];
__device__ float g_xm  [(long)BD*LD*CD];
__device__ float g_hbuf[(long)BD*3*HIDN*LD];
__device__ float g_gg  [(long)BD*HIDN*LD];

// ---------------- helpers ----------------
__device__ __forceinline__ float wsum(float v) {
#pragma unroll
    for (int o = 16; o > 0; o >>= 1) v += __shfl_xor_sync(0xffffffffu, v, o);
    return v;
}

__device__ __forceinline__ unsigned f2tf(float f) {
    unsigned r;
    asm("cvt.rna.tf32.f32 %0, %1;" : "=r"(r) : "f"(f));
    return r;
}

__device__ __forceinline__ void mma_tf32(float* d, const unsigned* a, const unsigned* b) {
    asm volatile(
        "mma.sync.aligned.m16n8k8.row.col.f32.tf32.tf32.f32 "
        "{%0,%1,%2,%3},{%4,%5,%6,%7},{%8,%9},{%0,%1,%2,%3};"
        : "+f"(d[0]), "+f"(d[1]), "+f"(d[2]), "+f"(d[3])
        : "r"(a[0]), "r"(a[1]), "r"(a[2]), "r"(a[3]), "r"(b[0]), "r"(b[1]));
}

// ---------------- fused double LayerNorm: x -> x1 (B,C,L), xn (B,L,C) ----------------
__global__ void __launch_bounds__(256) ln_double_k(
    const float* __restrict__ x,
    const float* __restrict__ w1, const float* __restrict__ b1,
    const float* __restrict__ w2, const float* __restrict__ b2)
{
    int gw = (blockIdx.x * 256 + threadIdx.x) >> 5;   // warp = one (b,l)
    int lane = threadIdx.x & 31;
    int b = gw >> 12;
    int l = gw & 4095;
    const float* xp = x + (long)b * CD * LD + l;
    float v[3];
#pragma unroll
    for (int i = 0; i < 3; i++) v[i] = xp[(long)(lane + 32 * i) * LD];
    float u = wsum(v[0] + v[1] + v[2]) * (1.f / 96.f);
    float q = 0.f;
#pragma unroll
    for (int i = 0; i < 3; i++) { float t = v[i] - u; q += t * t; }
    q = wsum(q);
    float rs = rsqrtf(q * (1.f / 96.f) + 1e-6f);
    float x1v[3];
    float* x1p = g_x1 + (long)b * CD * LD + l;
#pragma unroll
    for (int i = 0; i < 3; i++) {
        int cc = lane + 32 * i;
        x1v[i] = w1[cc] * (v[i] - u) * rs + b1[cc];
        x1p[(long)cc * LD] = x1v[i];
    }
    float u2 = wsum(x1v[0] + x1v[1] + x1v[2]) * (1.f / 96.f);
    float q2 = 0.f;
#pragma unroll
    for (int i = 0; i < 3; i++) { float t = x1v[i] - u2; q2 += t * t; }
    q2 = wsum(q2);
    float rs2 = rsqrtf(q2 * (1.f / 96.f) + 1e-5f);
    float* xnp = g_xn + ((long)b * LD + l) * CD;
#pragma unroll
    for (int i = 0; i < 3; i++) {
        int cc = lane + 32 * i;
        xnp[cc] = (x1v[i] - u2) * rs2 * w2[cc] + b2[cc];
    }
}

// ---------------- single channel-LN: g_xmid -> g_xm (B,L,C) ----------------
__global__ void __launch_bounds__(256) ln_single_k(
    const float* __restrict__ w1, const float* __restrict__ b1)
{
    int gw = (blockIdx.x * 256 + threadIdx.x) >> 5;
    int lane = threadIdx.x & 31;
    int b = gw >> 12;
    int l = gw & 4095;
    const float* xp = g_xmid + (long)b * CD * LD + l;
    float v[3];
#pragma unroll
    for (int i = 0; i < 3; i++) v[i] = xp[(long)(lane + 32 * i) * LD];
    float u = wsum(v[0] + v[1] + v[2]) * (1.f / 96.f);
    float q = 0.f;
#pragma unroll
    for (int i = 0; i < 3; i++) { float t = v[i] - u; q += t * t; }
    q = wsum(q);
    float rs = rsqrtf(q * (1.f / 96.f) + 1e-6f);
    float* xmp = g_xm + ((long)b * LD + l) * CD;
#pragma unroll
    for (int i = 0; i < 3; i++) {
        int cc = lane + 32 * i;
        xmp[cc] = w1[cc] * (v[i] - u) * rs + b1[cc];
    }
}

// ---------------- TF32 tensor-core GEMM ----------------
// C[M,N] = A[M,K] * (BT ? B[N,K]^T : B[K,N]); K % 16 == 0.
// Block tile 128x64, BK=16, 256 threads (8 warps, 4x2 warp grid, 32x32 warp tiles).
// SMEM stored [k][m]/[k][n] with +8 padding -> conflict-free fragment reads.
// EPI==1: C[m,n] = resid[m,n] + gmul[m]*acc.
#define SA 136
#define SB 72
template<bool BT, int EPI>
__global__ void __launch_bounds__(256) mma_gemm_k(
    const float* __restrict__ A, const float* __restrict__ B, float* __restrict__ C,
    int M, int N, int K, long sA, long sB, long sC,
    const float* __restrict__ gmul, const float* __restrict__ resid, long sR)
{
    __shared__ unsigned As[2][16][SA];
    __shared__ unsigned Bs[2][16][SB];
    A += (long)blockIdx.z * sA;
    B += (long)blockIdx.z * sB;
    C += (long)blockIdx.z * sC;
    if (EPI) resid += (long)blockIdx.z * sR;

    const int tid = threadIdx.x;
    const int m0 = blockIdx.y << 7, n0 = blockIdx.x << 6;

    // fill-thread mapping: conflict-free SMEM stores
    const int tr = tid & 63;            // row (A) / col (B, BT) index
    const int tk = (tid >> 6) << 2;     // 4 k-columns per thread

    const int wid = tid >> 5, lane = tid & 31;
    const int wm = (wid >> 1) << 5, wn = (wid & 1) << 5;
    const int gid = lane >> 2, tig = lane & 3;

    float acc[2][4][4];
#pragma unroll
    for (int f = 0; f < 2; f++)
#pragma unroll
        for (int g = 0; g < 4; g++)
#pragma unroll
            for (int i = 0; i < 4; i++) acc[f][g][i] = 0.f;

    const int nk = K >> 4;

    // ---- tile loader ----
    auto load_tile = [&](int buf, int k0) {
        // A: rows tr and tr+64, k-cols tk..tk+3
#pragma unroll
        for (int h = 0; h < 2; h++) {
            int m = m0 + tr + (h << 6);
            float4 v = make_float4(0.f, 0.f, 0.f, 0.f);
            if (m < M) v = *(const float4*)(A + (long)m * K + k0 + tk);
            As[buf][tk + 0][tr + (h << 6)] = f2tf(v.x);
            As[buf][tk + 1][tr + (h << 6)] = f2tf(v.y);
            As[buf][tk + 2][tr + (h << 6)] = f2tf(v.z);
            As[buf][tk + 3][tr + (h << 6)] = f2tf(v.w);
        }
        if (BT) {
            int n = n0 + tr;
            float4 v = make_float4(0.f, 0.f, 0.f, 0.f);
            if (n < N) v = *(const float4*)(B + (long)n * K + k0 + tk);
            Bs[buf][tk + 0][tr] = f2tf(v.x);
            Bs[buf][tk + 1][tr] = f2tf(v.y);
            Bs[buf][tk + 2][tr] = f2tf(v.z);
            Bs[buf][tk + 3][tr] = f2tf(v.w);
        } else {
#pragma unroll
            for (int j = 0; j < 4; j++) {
                int n = n0 + tr;
                float v = (n < N) ? B[(long)(k0 + tk + j) * N + n] : 0.f;
                Bs[buf][tk + j][tr] = f2tf(v);
            }
        }
    };

    load_tile(0, 0);
    __syncthreads();

    for (int t = 0; t < nk; t++) {
        if (t + 1 < nk) load_tile((t + 1) & 1, (t + 1) << 4);
        const int buf = t & 1;
#pragma unroll
        for (int kk = 0; kk < 2; kk++) {
            const int kb = kk << 3;
            unsigned a[2][4], b[4][2];
#pragma unroll
            for (int f = 0; f < 2; f++) {
                int mb = wm + (f << 4) + gid;
                a[f][0] = As[buf][kb + tig][mb];
                a[f][1] = As[buf][kb + tig][mb + 8];
                a[f][2] = As[buf][kb + tig + 4][mb];
                a[f][3] = As[buf][kb + tig + 4][mb + 8];
            }
#pragma unroll
            for (int g = 0; g < 4; g++) {
                int nb = wn + (g << 3) + gid;
                b[g][0] = Bs[buf][kb + tig][nb];
                b[g][1] = Bs[buf][kb + tig + 4][nb];
            }
#pragma unroll
            for (int f = 0; f < 2; f++)
#pragma unroll
                for (int g = 0; g < 4; g++)
                    mma_tf32(acc[f][g], a[f], b[g]);
        }
        __syncthreads();
    }

    // ---- epilogue ----
#pragma unroll
    for (int f = 0; f < 2; f++) {
#pragma unroll
        for (int h = 0; h < 2; h++) {
            int m = m0 + wm + (f << 4) + gid + (h << 3);
            if (m >= M) continue;
#pragma unroll
            for (int g = 0; g < 4; g++) {
#pragma unroll
                for (int j = 0; j < 2; j++) {
                    int n = n0 + wn + (g << 3) + (tig << 1) + j;
                    if (n >= N) continue;
                    float v = acc[f][g][(h << 1) + j];
                    if (EPI) v = resid[(long)m * N + n] + gmul[m] * v;
                    C[(long)m * N + n] = v;
                }
            }
        }
    }
}

// ---------------- causal depthwise conv(k=4) + SiLU; dir=1 reads reversed sequence ----------------
__global__ void __launch_bounds__(256) conv_silu_k(
    int dir, const float* __restrict__ cw, const float* __restrict__ cb)
{
    long idx = (long)blockIdx.x * 256 + threadIdx.x;   // B*L*DI
    int d = (int)(idx % DI);
    int t = (int)((idx / DI) % LD);
    int b = (int)(idx / ((long)DI * LD));
    float acc = cb[d];
#pragma unroll
    for (int k = 0; k < 4; k++) {
        int tt = t - 3 + k;
        if (tt >= 0) {
            int l = dir ? (LD - 1 - tt) : tt;
            acc += cw[d * 4 + k] * g_xz[dir][((long)b * LD + l) * 384 + d];
        }
    }
    g_xs[dir][idx] = acc / (1.f + __expf(-acc));
}

// ---------------- delta = softplus(dt @ Wdt^T + bdt) ----------------
__global__ void __launch_bounds__(256) delta_k(
    int dir, const float* __restrict__ Wdt, const float* __restrict__ bdt)
{
    long idx = (long)blockIdx.x * 256 + threadIdx.x;   // B*L*DI
    int d = (int)(idx % DI);
    long bt = idx / DI;
    const float* row = g_xdbl[dir] + bt * 38;
    float acc = bdt[d];
#pragma unroll
    for (int r = 0; r < 6; r++) acc += row[r] * Wdt[d * 6 + r];
    g_delta[dir][idx] = (acc > 20.f) ? acc : log1pf(__expf(acc));
}

// ---------------- chunked selective scan, phase 1 ----------------
__global__ void __launch_bounds__(192) scan_p1(int dir, const float* __restrict__ Alog)
{
    int c = blockIdx.x, b = blockIdx.y, d = threadIdx.x;
    __shared__ __align__(16) float sB[CT * 16];
    const float* xd = g_xdbl[dir] + ((long)b * LD + (long)c * CT) * 38;
    for (int i = d; i < CT * 16; i += 192) {
        int t = i >> 4, s = i & 15;
        sB[i] = xd[t * 38 + 6 + s];
    }
    float Ad[16];
#pragma unroll
    for (int s = 0; s < 16; s++) Ad[s] = -__expf(Alog[d * 16 + s]);
    __syncthreads();
    float h[16];
#pragma unroll
    for (int s = 0; s < 16; s++) h[s] = 0.f;
    float sd = 0.f;
    const float* dp = g_delta[dir] + ((long)b * LD + (long)c * CT) * DI + d;
    const float* xp = g_xs[dir]    + ((long)b * LD + (long)c * CT) * DI + d;
    for (int t = 0; t < CT; t++) {
        float dl = dp[(long)t * DI];
        float xv = xp[(long)t * DI];
        float u = dl * xv;
        sd += dl;
        const float* bt = &sB[t * 16];
#pragma unroll
        for (int s = 0; s < 16; s++)
            h[s] = __expf(Ad[s] * dl) * h[s] + u * bt[s];
    }
    float* hp = g_chH[dir] + (((long)b * NC + c) * DI + d) * 16;
#pragma unroll
    for (int s = 0; s < 16; s++) hp[s] = h[s];
    g_chD[dir][((long)b * NC + c) * DI + d] = sd;
}

// ---------------- phase 2: sequential inter-chunk combine ----------------
__global__ void __launch_bounds__(192) scan_p2(
    const float* __restrict__ AlogF, const float* __restrict__ AlogB)
{
    int b = blockIdx.x, dir = blockIdx.y, d = threadIdx.x;
    const float* Alog = dir ? AlogB : AlogF;
    float Ad[16];
#pragma unroll
    for (int s = 0; s < 16; s++) Ad[s] = -__expf(Alog[d * 16 + s]);
    float h[16];
#pragma unroll
    for (int s = 0; s < 16; s++) h[s] = 0.f;
    for (int c = 0; c < NC; c++) {
        float sd = g_chD[dir][((long)b * NC + c) * DI + d];
        float* hp = g_chH[dir] + (((long)b * NC + c) * DI + d) * 16;
#pragma unroll
        for (int s = 0; s < 16; s++) {
            float a = __expf(Ad[s] * sd);
            float loc = hp[s];
            hp[s] = h[s];                // store h_start for this chunk
            h[s] = a * h[s] + loc;
        }
    }
}

// ---------------- phase 3: recompute with correct h_start, emit y*silu(z) ----------------
__global__ void __launch_bounds__(192) scan_p3(
    int dir, const float* __restrict__ Alog, const float* __restrict__ Dp)
{
    int c = blockIdx.x, b = blockIdx.y, d = threadIdx.x;
    __shared__ __align__(16) float sB[CT * 16];
    __shared__ __align__(16) float sC[CT * 16];
    const float* xd = g_xdbl[dir] + ((long)b * LD + (long)c * CT) * 38;
    for (int i = d; i < CT * 16; i += 192) {
        int t = i >> 4, s = i & 15;
        sB[i] = xd[t * 38 + 6 + s];
        sC[i] = xd[t * 38 + 22 + s];
    }
    float Ad[16];
#pragma unroll
    for (int s = 0; s < 16; s++) Ad[s] = -__expf(Alog[d * 16 + s]);
    float Dd = Dp[d];
    __syncthreads();
    const float* hp = g_chH[dir] + (((long)b * NC + c) * DI + d) * 16;
    float h[16];
#pragma unroll
    for (int s = 0; s < 16; s++) h[s] = hp[s];
    const float* dp = g_delta[dir] + ((long)b * LD + (long)c * CT) * DI + d;
    const float* xp = g_xs[dir]    + ((long)b * LD + (long)c * CT) * DI + d;
    for (int t = 0; t < CT; t++) {
        float dl = dp[(long)t * DI];
        float xv = xp[(long)t * DI];
        float u = dl * xv;
        const float* bt = &sB[t * 16];
        const float* ct = &sC[t * 16];
        float y = 0.f;
#pragma unroll
        for (int s = 0; s < 16; s++) {
            h[s] = __expf(Ad[s] * dl) * h[s] + u * bt[s];
            y += h[s] * ct[s];
        }
        int tg = c * CT + t;
        int lo = dir ? (LD - 1 - tg) : tg;
        float zv = g_xz[dir][((long)b * LD + lo) * 384 + 192 + d];
        float val = (y + xv * Dd) * (zv / (1.f + __expf(-zv)));
        long oi = ((long)b * LD + lo) * DI + d;
        if (dir) g_comb[oi] += val;
        else     g_comb[oi] = val;
    }
}

// ---------------- residual 1: xmid = x + gamma1*(yo + x1) ----------------
__global__ void __launch_bounds__(256) resid1_k(
    const float* __restrict__ x, const float* __restrict__ gamma1)
{
    long idx = (long)blockIdx.x * 256 + threadIdx.x;   // B*C*L
    int l = (int)(idx % LD);
    int c = (int)((idx / LD) % CD);
    int b = (int)(idx / ((long)CD * LD));
    float yov = g_yo[((long)b * LD + l) * CD + c];
    g_xmid[idx] = x[idx] + gamma1[c] * (yov + g_x1[idx]);
}

// ---------------- MSFF gate: g = gelu(dw1(h1)) * dw2(h2) * dw3(h3) ----------------
__device__ __forceinline__ float dwc9(const float* __restrict__ p,
                                      const float* __restrict__ w,
                                      int y, int x, int dil)
{
    float acc = 0.f;
#pragma unroll
    for (int ky = 0; ky < 3; ky++) {
        int yy = y + (ky - 1) * dil;
        if (yy < 0 || yy >= HD) continue;
#pragma unroll
        for (int kx = 0; kx < 3; kx++) {
            int xx = x + (kx - 1) * dil;
            if (xx < 0 || xx >= WD) continue;
            acc += w[ky * 3 + kx] * p[yy * WD + xx];
        }
    }
    return acc;
}

__global__ void __launch_bounds__(256) gate_k(
    const float* __restrict__ dw1, const float* __restrict__ dw2, const float* __restrict__ dw3)
{
    long idx = (long)blockIdx.x * 256 + threadIdx.x;   // B*HIDN*L
    int l = (int)(idx % LD);
    int j = (int)((idx / LD) % HIDN);
    int b = (int)(idx / ((long)HIDN * LD));
    int y = l >> 6, x = l & 63;
    const float* hb = g_hbuf + (long)b * 3 * HIDN * LD;
    float a1 = dwc9(hb + (long)j * LD,              dw1 + j * 9, y, x, 1);
    float a2 = dwc9(hb + (long)(HIDN + j) * LD,     dw2 + j * 9, y, x, 2);
    float a3 = dwc9(hb + (long)(2 * HIDN + j) * LD, dw3 + j * 9, y, x, 3);
    float ge = 0.5f * a1 * (1.f + erff(a1 * 0.70710678118654752f));
    g_gg[idx] = ge * a2 * a3;
}

// ---------------- host ----------------
extern "C" void kernel_launch(void* const* d_in, const int* in_sizes, int n_in,
                              void* d_out, int out_size)
{
    const float* x      = (const float*)d_in[0];
    const float* gamma1 = (const float*)d_in[1];
    const float* gamma2 = (const float*)d_in[2];
    const float* ln1w   = (const float*)d_in[3];
    const float* ln1b   = (const float*)d_in[4];
    const float* mnw    = (const float*)d_in[5];
    const float* mnb    = (const float*)d_in[6];
    const float* Win[2]   = {(const float*)d_in[7],  (const float*)d_in[15]};
    const float* convw[2] = {(const float*)d_in[8],  (const float*)d_in[16]};
    const float* convb[2] = {(const float*)d_in[9],  (const float*)d_in[17]};
    const float* Wx[2]    = {(const float*)d_in[10], (const float*)d_in[18]};
    const float* Wdt[2]   = {(const float*)d_in[11], (const float*)d_in[19]};
    const float* bdt[2]   = {(const float*)d_in[12], (const float*)d_in[20]};
    const float* Alog[2]  = {(const float*)d_in[13], (const float*)d_in[21]};
    const float* Dp[2]    = {(const float*)d_in[14], (const float*)d_in[22]};
    const float* Wout   = (const float*)d_in[23];
    const float* mwin   = (const float*)d_in[24];
    const float* dw1    = (const float*)d_in[25];
    const float* dw2    = (const float*)d_in[26];
    const float* dw3    = (const float*)d_in[27];
    const float* mwout  = (const float*)d_in[28];
    float* out = (float*)d_out;

    float *p_xn, *p_xz, *p_xs, *p_xdbl, *p_comb, *p_yo, *p_xm, *p_hbuf, *p_gg, *p_xmid;
    cudaGetSymbolAddress((void**)&p_xn,   g_xn);
    cudaGetSymbolAddress((void**)&p_xz,   g_xz);
    cudaGetSymbolAddress((void**)&p_xs,   g_xs);
    cudaGetSymbolAddress((void**)&p_xdbl, g_xdbl);
    cudaGetSymbolAddress((void**)&p_comb, g_comb);
    cudaGetSymbolAddress((void**)&p_yo,   g_yo);
    cudaGetSymbolAddress((void**)&p_xm,   g_xm);
    cudaGetSymbolAddress((void**)&p_hbuf, g_hbuf);
    cudaGetSymbolAddress((void**)&p_gg,   g_gg);
    cudaGetSymbolAddress((void**)&p_xmid, g_xmid);

    const long XZS = (long)BD * LD * 384;
    const long XSS = (long)BD * LD * DI;
    const long XDS = (long)BD * LD * 38;

    // 1. LN pair
    ln_double_k<<<1024, 256>>>(x, ln1w, ln1b, mnw, mnb);

    // 2. xz = xn @ Win^T (per direction)   M=8192 N=384 K=96
    for (int dir = 0; dir < 2; dir++)
        mma_gemm_k<true, 0><<<dim3(6, 64, 1), 256>>>(
            p_xn, Win[dir], p_xz + dir * XZS, BD * LD, 384, CD, 0, 0, 0, nullptr, nullptr, 0);

    // 3. causal conv + silu
    for (int dir = 0; dir < 2; dir++)
        conv_silu_k<<<(int)(((long)BD * LD * DI) / 256), 256>>>(dir, convw[dir], convb[dir]);

    // 4. x_dbl = xs @ Wx^T   M=8192 N=38 K=192
    for (int dir = 0; dir < 2; dir++)
        mma_gemm_k<true, 0><<<dim3(1, 64, 1), 256>>>(
            p_xs + dir * XSS, Wx[dir], p_xdbl + dir * XDS, BD * LD, 38, DI, 0, 0, 0, nullptr, nullptr, 0);

    // 5. delta
    for (int dir = 0; dir < 2; dir++)
        delta_k<<<(int)(((long)BD * LD * DI) / 256), 256>>>(dir, Wdt[dir], bdt[dir]);

    // 6. chunked scan
    for (int dir = 0; dir < 2; dir++)
        scan_p1<<<dim3(NC, BD), 192>>>(dir, Alog[dir]);
    scan_p2<<<dim3(BD, 2), 192>>>(Alog[0], Alog[1]);
    scan_p3<<<dim3(NC, BD), 192>>>(0, Alog[0], Dp[0]);
    scan_p3<<<dim3(NC, BD), 192>>>(1, Alog[1], Dp[1]);

    // 7. yo = comb @ Wout^T   M=8192 N=96 K=192
    mma_gemm_k<true, 0><<<dim3(2, 64, 1), 256>>>(
        p_comb, Wout, p_yo, BD * LD, CD, DI, 0, 0, 0, nullptr, nullptr, 0);

    // 8. first residual
    resid1_k<<<(int)(((long)BD * CD * LD) / 256), 256>>>(x, gamma1);

    // 9. xm = ln_cf(xmid)
    ln_single_k<<<1024, 256>>>(ln1w, ln1b);

    // 10. h = msff_win @ xm^T  (batched, M=576 N=4096 K=96)
    mma_gemm_k<true, 0><<<dim3(64, 5, BD), 256>>>(
        mwin, p_xm, p_hbuf, 3 * HIDN, LD, CD,
        0, (long)LD * CD, (long)3 * HIDN * LD, nullptr, nullptr, 0);

    // 11. gated multiscale dwconv
    gate_k<<<(int)(((long)BD * HIDN * LD) / 256), 256>>>(dw1, dw2, dw3);

    // 12. out = xmid + gamma2 * (msff_wout @ g)   (batched, M=96 N=4096 K=192, fused residual)
    mma_gemm_k<false, 1><<<dim3(64, 1, BD), 256>>>(
        mwout, p_gg, out, CD, LD, HIDN,
        0, (long)HIDN * LD, (long)CD * LD, gamma2, p_xmid, (long)CD * LD);
}